// round 1
// baseline (speedup 1.0000x reference)
#include <cuda_runtime.h>
#include <math.h>

// Problem constants
#define B 32
#define S 2048
#define H 1024
#define R 64

// Scratch (no allocations allowed -> __device__ globals)
__device__ float g_ae[B * H];                // answer_emb [B,H]
__device__ float g_u[B * H];                 // u = W @ answer_emb, [B,H]
__device__ float g_scores[B * R];            // raw scores
__device__ unsigned char g_mask[B * R];      // canonicalized rubric_mask

// ---------------------------------------------------------------------------
// Kernel 0: canonicalize rubric_mask. The harness may pass numpy bool (1 byte)
// or int32 (4 bytes). Detect on-device: if encoded as int32 with values {0,1},
// every byte at offset %4 != 0 is zero. A 1-byte bool mask (~80% true) has
// nonzero bytes there with probability 1 - 0.2^1536.
// ---------------------------------------------------------------------------
__global__ void k_mask(const unsigned char* __restrict__ raw) {
    __shared__ int s_any;
    if (threadIdx.x == 0) s_any = 0;
    __syncthreads();
    int any = 0;
    for (int i = threadIdx.x; i < B * R; i += blockDim.x)
        if (i & 3) any |= raw[i];
    if (any) atomicOr(&s_any, 1);
    __syncthreads();
    const int is_bool = s_any;
    const int* raw32 = (const int*)raw;
    for (int i = threadIdx.x; i < B * R; i += blockDim.x)
        g_mask[i] = is_bool ? (raw[i] != 0) : (raw32[i] != 0);
}

// ---------------------------------------------------------------------------
// Kernel 1: answer_emb[b,:] = mean over answer span rows. 32 blocks x 256 thr,
// each thread owns one float4 of the H dimension.
// ---------------------------------------------------------------------------
__global__ void k_answer(const float* __restrict__ seq,
                         const int* __restrict__ aspan) {
    int b = blockIdx.x;
    int s0 = aspan[b * 2], s1 = aspan[b * 2 + 1];
    float inv = 1.0f / (float)(s1 - s0);
    int t = threadIdx.x;  // float4 index 0..255
    const float4* base = (const float4*)(seq + (size_t)b * S * H);
    float4 acc = make_float4(0.f, 0.f, 0.f, 0.f);
    for (int s = s0; s < s1; s++) {
        float4 e = __ldg(base + s * (H / 4) + t);
        acc.x += e.x; acc.y += e.y; acc.z += e.z; acc.w += e.w;
    }
    float4 r = make_float4(acc.x * inv, acc.y * inv, acc.z * inv, acc.w * inv);
    ((float4*)g_ae)[b * (H / 4) + t] = r;
}

// ---------------------------------------------------------------------------
// Kernel 2: u[b,h] = sum_k W[h,k] * ae[b,k]. Read W exactly once from HBM;
// ae (128 KB) stays L1-resident per SM. Grid 256 blocks (4 h-rows each),
// 256 threads = 8 warps; warp w owns 4 batches {4w..4w+3}; lanes stripe k.
// 32 lane-FMAs per W element loaded.
// ---------------------------------------------------------------------------
__global__ void k_u(const float* __restrict__ W) {
    int h0 = blockIdx.x * 4;
    int wrp = threadIdx.x >> 5;
    int lane = threadIdx.x & 31;
    int bbase = wrp * 4;

    const float4* a0 = (const float4*)(g_ae + (size_t)(bbase + 0) * H);
    const float4* a1 = (const float4*)(g_ae + (size_t)(bbase + 1) * H);
    const float4* a2 = (const float4*)(g_ae + (size_t)(bbase + 2) * H);
    const float4* a3 = (const float4*)(g_ae + (size_t)(bbase + 3) * H);

    for (int hh = 0; hh < 4; hh++) {
        int h = h0 + hh;
        const float4* wrow = (const float4*)(W + (size_t)h * H);
        float acc0 = 0.f, acc1 = 0.f, acc2 = 0.f, acc3 = 0.f;
        #pragma unroll
        for (int kc = 0; kc < 8; kc++) {
            int ki = kc * 32 + lane;  // float4 index into the H dim
            float4 w4 = __ldg(wrow + ki);
            float4 x;
            x = __ldg(a0 + ki);
            acc0 += w4.x * x.x + w4.y * x.y + w4.z * x.z + w4.w * x.w;
            x = __ldg(a1 + ki);
            acc1 += w4.x * x.x + w4.y * x.y + w4.z * x.z + w4.w * x.w;
            x = __ldg(a2 + ki);
            acc2 += w4.x * x.x + w4.y * x.y + w4.z * x.z + w4.w * x.w;
            x = __ldg(a3 + ki);
            acc3 += w4.x * x.x + w4.y * x.y + w4.z * x.z + w4.w * x.w;
        }
        #pragma unroll
        for (int off = 16; off; off >>= 1) {
            acc0 += __shfl_xor_sync(0xffffffffu, acc0, off);
            acc1 += __shfl_xor_sync(0xffffffffu, acc1, off);
            acc2 += __shfl_xor_sync(0xffffffffu, acc2, off);
            acc3 += __shfl_xor_sync(0xffffffffu, acc3, off);
        }
        if (lane == 0) {
            g_u[(size_t)(bbase + 0) * H + h] = acc0;
            g_u[(size_t)(bbase + 1) * H + h] = acc1;
            g_u[(size_t)(bbase + 2) * H + h] = acc2;
            g_u[(size_t)(bbase + 3) * H + h] = acc3;
        }
    }
}

// ---------------------------------------------------------------------------
// Kernel 3: scores[b,r] = (1/len) * sum_{s in span} seq[b,s,:] . u[b,:]
// Grid (R, B); 256 threads, thread t owns float4 t of H. This is the
// HBM-bound kernel: adjacent r-blocks of a batch share rows via L2.
// ---------------------------------------------------------------------------
__global__ void k_scores(const float* __restrict__ seq,
                         const int* __restrict__ rspan) {
    int r = blockIdx.x, b = blockIdx.y;
    int idx = b * R + r;
    int t = threadIdx.x;
    if (!g_mask[idx]) {
        if (t == 0) g_scores[idx] = -INFINITY;
        return;
    }
    int s0 = rspan[idx * 2], s1 = rspan[idx * 2 + 1];
    float4 u4 = __ldg((const float4*)(g_u + (size_t)b * H) + t);
    const float4* base = (const float4*)(seq + (size_t)b * S * H);
    float acc = 0.f;
    for (int s = s0; s < s1; s++) {
        float4 e = __ldg(base + s * (H / 4) + t);
        acc += e.x * u4.x + e.y * u4.y + e.z * u4.z + e.w * u4.w;
    }
    // block reduce 256 -> 1
    __shared__ float sred[8];
    #pragma unroll
    for (int off = 16; off; off >>= 1)
        acc += __shfl_xor_sync(0xffffffffu, acc, off);
    if ((t & 31) == 0) sred[t >> 5] = acc;
    __syncthreads();
    if (t < 8) {
        float v = sred[t];
        #pragma unroll
        for (int off = 4; off; off >>= 1)
            v += __shfl_xor_sync(0xffu, v, off);
        if (t == 0) g_scores[idx] = v / (float)(s1 - s0);
    }
}

// ---------------------------------------------------------------------------
// Kernel 4: masked softmax over R=64 per batch. (bias b[0] is a constant
// shift -> cancels in softmax, skipped.)
// ---------------------------------------------------------------------------
__global__ void k_softmax(float* __restrict__ out) {
    int b = blockIdx.x;
    int t = threadIdx.x;  // 0..63
    int idx = b * R + t;
    float v = g_mask[idx] ? g_scores[idx] : -INFINITY;

    __shared__ float sm[2];
    float m = v;
    #pragma unroll
    for (int off = 16; off; off >>= 1)
        m = fmaxf(m, __shfl_xor_sync(0xffffffffu, m, off));
    if ((t & 31) == 0) sm[t >> 5] = m;
    __syncthreads();
    m = fmaxf(sm[0], sm[1]);
    __syncthreads();  // before reusing sm[]

    float e = (v == -INFINITY) ? 0.0f : expf(v - m);
    float s = e;
    #pragma unroll
    for (int off = 16; off; off >>= 1)
        s += __shfl_xor_sync(0xffffffffu, s, off);
    if ((t & 31) == 0) sm[t >> 5] = s;
    __syncthreads();
    s = sm[0] + sm[1];

    out[idx] = e / s;
}

// ---------------------------------------------------------------------------
// Launch. Inputs identified by unique element counts (robust to ordering):
//   seq_embeddings: 67108864, W: 1048576, b: 1, rubric_span: 4096,
//   answer_span: 64, rubric_mask: 2048
// ---------------------------------------------------------------------------
extern "C" void kernel_launch(void* const* d_in, const int* in_sizes, int n_in,
                              void* d_out, int out_size) {
    const float* seq = nullptr;
    const float* W = nullptr;
    const int* rspan = nullptr;
    const int* aspan = nullptr;
    const unsigned char* mask = nullptr;

    for (int i = 0; i < n_in; i++) {
        switch (in_sizes[i]) {
            case B * S * H: seq   = (const float*)d_in[i]; break;
            case H * H:     W     = (const float*)d_in[i]; break;
            case B * R * 2: rspan = (const int*)d_in[i]; break;
            case B * 2:     aspan = (const int*)d_in[i]; break;
            case B * R:     mask  = (const unsigned char*)d_in[i]; break;
            default: break;  // bias (size 1): cancels in softmax
        }
    }

    float* out = (float*)d_out;

    k_mask<<<1, 256>>>(mask);
    k_answer<<<B, 256>>>(seq, aspan);
    k_u<<<H / 4, 256>>>(W);
    dim3 gs(R, B);
    k_scores<<<gs, 256>>>(seq, rspan);
    k_softmax<<<B, R>>>(out);
}

// round 2
// speedup vs baseline: 1.0095x; 1.0095x over previous
#include <cuda_runtime.h>
#include <math.h>

// Problem constants
#define B 32
#define S 2048
#define H 1024
#define R 64
#define HV4 (H / 4)   // 256 float4 per row

// Scratch (no allocations allowed -> __device__ globals)
__device__ float g_ae[B * H];                // answer_emb [B,H]
__device__ float g_u[B * H];                 // u = W @ answer_emb, [B,H]
__device__ float g_scores[B * R];            // raw scores
__device__ unsigned char g_mask[B * R];      // canonicalized rubric_mask

__device__ __forceinline__ float dot4(float4 a, float4 b) {
    return a.x * b.x + a.y * b.y + a.z * b.z + a.w * b.w;
}

// ---------------------------------------------------------------------------
// Kernel 1 (fused): answer-span mean pooling + rubric_mask canonicalization.
// Grid = B*4 + 1 blocks, 64 threads.
//   blocks [0, B*4): block (b, seg) pools H-segment [seg*256, seg*256+256)
//                    over the answer span (s-loop unrolled x4).
//   block B*4: canonicalizes rubric_mask (detects 1-byte bool vs int32).
// ---------------------------------------------------------------------------
__global__ void k_answer_mask(const float* __restrict__ seq,
                              const int* __restrict__ aspan,
                              const unsigned char* __restrict__ rawmask) {
    if (blockIdx.x == B * 4) {
        // mask canonicalization: int32-encoded {0,1} has zero bytes at i%4!=0
        __shared__ int s_any;
        if (threadIdx.x == 0) s_any = 0;
        __syncthreads();
        int any = 0;
        for (int i = threadIdx.x; i < B * R; i += blockDim.x)
            if (i & 3) any |= rawmask[i];
        if (any) atomicOr(&s_any, 1);
        __syncthreads();
        const int is_bool = s_any;
        const int* raw32 = (const int*)rawmask;
        for (int i = threadIdx.x; i < B * R; i += blockDim.x)
            g_mask[i] = is_bool ? (rawmask[i] != 0) : (raw32[i] != 0);
        return;
    }
    int b = blockIdx.x >> 2;
    int seg = blockIdx.x & 3;
    int s0 = __ldg(aspan + b * 2), s1 = __ldg(aspan + b * 2 + 1);
    float inv = 1.0f / (float)(s1 - s0);
    int t = seg * 64 + threadIdx.x;   // float4 column 0..255
    const float4* base = (const float4*)(seq + (size_t)b * S * H) + t;
    float4 a0 = make_float4(0, 0, 0, 0), a1 = a0, a2 = a0, a3 = a0;
    int s = s0;
    for (; s + 4 <= s1; s += 4) {
        float4 e0 = __ldg(base + (s + 0) * HV4);
        float4 e1 = __ldg(base + (s + 1) * HV4);
        float4 e2 = __ldg(base + (s + 2) * HV4);
        float4 e3 = __ldg(base + (s + 3) * HV4);
        a0.x += e0.x; a0.y += e0.y; a0.z += e0.z; a0.w += e0.w;
        a1.x += e1.x; a1.y += e1.y; a1.z += e1.z; a1.w += e1.w;
        a2.x += e2.x; a2.y += e2.y; a2.z += e2.z; a2.w += e2.w;
        a3.x += e3.x; a3.y += e3.y; a3.z += e3.z; a3.w += e3.w;
    }
    for (; s < s1; s++) {
        float4 e = __ldg(base + s * HV4);
        a0.x += e.x; a0.y += e.y; a0.z += e.z; a0.w += e.w;
    }
    float4 r;
    r.x = (a0.x + a1.x + a2.x + a3.x) * inv;
    r.y = (a0.y + a1.y + a2.y + a3.y) * inv;
    r.z = (a0.z + a1.z + a2.z + a3.z) * inv;
    r.w = (a0.w + a1.w + a2.w + a3.w) * inv;
    ((float4*)g_ae)[b * HV4 + t] = r;
}

// ---------------------------------------------------------------------------
// Kernel 2: u[b,h] = sum_k W[h,k] * ae[b,k]. W read exactly once; ae (128 KB)
// L1/L2-resident. 256 blocks x 256 threads; warp w owns 4 batches.
// ---------------------------------------------------------------------------
__global__ void k_u(const float* __restrict__ W) {
    int h0 = blockIdx.x * 4;
    int wrp = threadIdx.x >> 5;
    int lane = threadIdx.x & 31;
    int bbase = wrp * 4;

    const float4* a0 = (const float4*)(g_ae + (size_t)(bbase + 0) * H);
    const float4* a1 = (const float4*)(g_ae + (size_t)(bbase + 1) * H);
    const float4* a2 = (const float4*)(g_ae + (size_t)(bbase + 2) * H);
    const float4* a3 = (const float4*)(g_ae + (size_t)(bbase + 3) * H);

    for (int hh = 0; hh < 4; hh++) {
        int h = h0 + hh;
        const float4* wrow = (const float4*)(W + (size_t)h * H);
        float acc0 = 0.f, acc1 = 0.f, acc2 = 0.f, acc3 = 0.f;
        #pragma unroll
        for (int kc = 0; kc < 8; kc++) {
            int ki = kc * 32 + lane;
            float4 w4 = __ldg(wrow + ki);
            acc0 += dot4(w4, __ldg(a0 + ki));
            acc1 += dot4(w4, __ldg(a1 + ki));
            acc2 += dot4(w4, __ldg(a2 + ki));
            acc3 += dot4(w4, __ldg(a3 + ki));
        }
        #pragma unroll
        for (int off = 16; off; off >>= 1) {
            acc0 += __shfl_xor_sync(0xffffffffu, acc0, off);
            acc1 += __shfl_xor_sync(0xffffffffu, acc1, off);
            acc2 += __shfl_xor_sync(0xffffffffu, acc2, off);
            acc3 += __shfl_xor_sync(0xffffffffu, acc3, off);
        }
        if (lane == 0) {
            g_u[(size_t)(bbase + 0) * H + h] = acc0;
            g_u[(size_t)(bbase + 1) * H + h] = acc1;
            g_u[(size_t)(bbase + 2) * H + h] = acc2;
            g_u[(size_t)(bbase + 3) * H + h] = acc3;
        }
    }
}

// ---------------------------------------------------------------------------
// Kernel 3: scores[b,r] = (1/len) * sum_{s in span} seq[b,s,:] . u[b,:]
// Grid (R, B), 256 threads; s-loop unrolled x4 with independent accumulators
// so 4 row-loads/thread are in flight (raise HBM util past 53%).
// ---------------------------------------------------------------------------
__global__ void k_scores(const float* __restrict__ seq,
                         const int* __restrict__ rspan) {
    int r = blockIdx.x, b = blockIdx.y;
    int idx = b * R + r;
    int t = threadIdx.x;
    if (!g_mask[idx]) {
        if (t == 0) g_scores[idx] = -INFINITY;
        return;
    }
    int s0 = __ldg(rspan + idx * 2), s1 = __ldg(rspan + idx * 2 + 1);
    float4 u4 = __ldg((const float4*)(g_u + (size_t)b * H) + t);
    const float4* base = (const float4*)(seq + (size_t)b * S * H) + t;

    float a0 = 0.f, a1 = 0.f, a2 = 0.f, a3 = 0.f;
    int s = s0;
    for (; s + 4 <= s1; s += 4) {
        float4 e0 = __ldg(base + (s + 0) * HV4);
        float4 e1 = __ldg(base + (s + 1) * HV4);
        float4 e2 = __ldg(base + (s + 2) * HV4);
        float4 e3 = __ldg(base + (s + 3) * HV4);
        a0 += dot4(e0, u4);
        a1 += dot4(e1, u4);
        a2 += dot4(e2, u4);
        a3 += dot4(e3, u4);
    }
    for (; s < s1; s++)
        a0 += dot4(__ldg(base + s * HV4), u4);
    float acc = (a0 + a1) + (a2 + a3);

    // block reduce 256 -> 1
    __shared__ float sred[8];
    #pragma unroll
    for (int off = 16; off; off >>= 1)
        acc += __shfl_xor_sync(0xffffffffu, acc, off);
    if ((t & 31) == 0) sred[t >> 5] = acc;
    __syncthreads();
    if (t < 8) {
        float v = sred[t];
        #pragma unroll
        for (int off = 4; off; off >>= 1)
            v += __shfl_xor_sync(0xffu, v, off);
        if (t == 0) g_scores[idx] = v / (float)(s1 - s0);
    }
}

// ---------------------------------------------------------------------------
// Kernel 4: masked softmax over R=64 per batch (bias cancels in softmax).
// ---------------------------------------------------------------------------
__global__ void k_softmax(float* __restrict__ out) {
    int b = blockIdx.x;
    int t = threadIdx.x;  // 0..63
    int idx = b * R + t;
    float v = g_mask[idx] ? g_scores[idx] : -INFINITY;

    __shared__ float sm[2];
    float m = v;
    #pragma unroll
    for (int off = 16; off; off >>= 1)
        m = fmaxf(m, __shfl_xor_sync(0xffffffffu, m, off));
    if ((t & 31) == 0) sm[t >> 5] = m;
    __syncthreads();
    m = fmaxf(sm[0], sm[1]);
    __syncthreads();

    float e = (v == -INFINITY) ? 0.0f : expf(v - m);
    float s = e;
    #pragma unroll
    for (int off = 16; off; off >>= 1)
        s += __shfl_xor_sync(0xffffffffu, s, off);
    if ((t & 31) == 0) sm[t >> 5] = s;
    __syncthreads();
    s = sm[0] + sm[1];

    out[idx] = e / s;
}

// ---------------------------------------------------------------------------
// Launch. Inputs identified by unique element counts (robust to ordering):
//   seq: 67108864, W: 1048576, b: 1, rubric_span: 4096, answer_span: 64,
//   rubric_mask: 2048
// ---------------------------------------------------------------------------
extern "C" void kernel_launch(void* const* d_in, const int* in_sizes, int n_in,
                              void* d_out, int out_size) {
    const float* seq = nullptr;
    const float* W = nullptr;
    const int* rspan = nullptr;
    const int* aspan = nullptr;
    const unsigned char* mask = nullptr;

    for (int i = 0; i < n_in; i++) {
        switch (in_sizes[i]) {
            case B * S * H: seq   = (const float*)d_in[i]; break;
            case H * H:     W     = (const float*)d_in[i]; break;
            case B * R * 2: rspan = (const int*)d_in[i]; break;
            case B * 2:     aspan = (const int*)d_in[i]; break;
            case B * R:     mask  = (const unsigned char*)d_in[i]; break;
            default: break;  // bias (size 1): cancels in softmax
        }
    }

    float* out = (float*)d_out;

    k_answer_mask<<<B * 4 + 1, 64>>>(seq, aspan, mask);
    k_u<<<H / 4, 256>>>(W);
    dim3 gs(R, B);
    k_scores<<<gs, 256>>>(seq, rspan);
    k_softmax<<<B, R>>>(out);
}